// round 3
// baseline (speedup 1.0000x reference)
#include <cuda_runtime.h>
#include <cuda_fp16.h>

#define NN 96
#define NP 9216            // 96*96
#define NVOX 884736        // 96^3
#define NPAIR (NVOX / 2)   // float4 pair count per field
#define NFIELDS 8
#define NPAIRS 6
#define VSTEPS 7
#define TPB 256
#define NBLK (NVOX / TPB)  // 3456

// Each field stored as half4 (vx,vy,vz,pad) per voxel = 8 B, in TWO copies:
//  *_p : primary (element i at 8B offset 8i)  -> even-z0 pairs are 16B aligned
//  *_s : shifted by one element (slot j = element j+1) -> odd-z0 pairs 16B aligned
// Last slot of *_s is a guard (never written, stays 0 from .bss init).
__device__ float4 g_Ap[NFIELDS][NPAIR];
__device__ float4 g_As[NFIELDS][NPAIR];
__device__ float4 g_Bp[NFIELDS][NPAIR];
__device__ float4 g_Bs[NFIELDS][NPAIR];
__device__ float  g_Rt[NPAIRS][3][NVOX];   // transposed R: (pair, channel, voxel)
__device__ double g_part[NPAIRS * NBLK];

__device__ __forceinline__ float lp(float a, float b, float t) {
    return fmaf(t, b - a, a);
}

__device__ __forceinline__ uint2 packv(float x, float y, float z) {
    __half2 h0 = __floats2half2_rn(x, y);
    __half2 h1 = __floats2half2_rn(z, 0.f);
    uint2 u;
    u.x = *reinterpret_cast<unsigned*>(&h0);
    u.y = *reinterpret_cast<unsigned*>(&h1);
    return u;
}

__device__ __forceinline__ float3 unpack1(uint2 u) {
    float2 a = __half22float2(*reinterpret_cast<__half2*>(&u.x));
    float2 b = __half22float2(*reinterpret_cast<__half2*>(&u.y));
    return make_float3(a.x, a.y, b.x);
}

// Lerp across the z-pair packed in one float4 (voxel z0 in halves 0..3, z0+1 in 4..7)
__device__ __forceinline__ float3 zlerp(float4 q, float fz) {
    __half2* h = reinterpret_cast<__half2*>(&q);
    float2 a0 = __half22float2(h[0]);   // vx0, vy0
    float2 a1 = __half22float2(h[1]);   // vz0, pad
    float2 b0 = __half22float2(h[2]);   // vx1, vy1
    float2 b1 = __half22float2(h[3]);   // vz1, pad
    return make_float3(lp(a0.x, b0.x, fz), lp(a0.y, b0.y, fz), lp(a1.x, b1.x, fz));
}

// Trilinear sample with reference clamp semantics using paired-z loads:
// x0=clip(floor,0,95), x1=clip(x0+1,0,95); fractional part unclamped.
// z-pair (z0,z0+1) fetched as ONE LDG.128 from primary (z0 even) or shifted (z0 odd).
// z0==95 => z1==z0: force fz=0 so the (possibly garbage/guard) high half never blends.
__device__ __forceinline__ float3 trisample(const float4* __restrict__ pp,
                                            const float4* __restrict__ sh,
                                            float cx, float cy, float cz) {
    float xf = floorf(cx), yf = floorf(cy), zf = floorf(cz);
    float fx = cx - xf, fy = cy - yf, fz = cz - zf;
    int x0 = min(max((int)xf, 0), NN - 1); int x1 = min(x0 + 1, NN - 1);
    int y0 = min(max((int)yf, 0), NN - 1); int y1 = min(y0 + 1, NN - 1);
    int z0 = min(max((int)zf, 0), NN - 1);
    if (z0 == NN - 1) fz = 0.f;

    const float4* base = (z0 & 1) ? sh : pp;
    int zi = z0 >> 1;
    int r0 = x0 * (NP / 2), r1 = x1 * (NP / 2);
    int c0 = y0 * (NN / 2), c1 = y1 * (NN / 2);

    float3 s00 = zlerp(__ldg(base + r0 + c0 + zi), fz);
    float3 s01 = zlerp(__ldg(base + r0 + c1 + zi), fz);
    float3 s10 = zlerp(__ldg(base + r1 + c0 + zi), fz);
    float3 s11 = zlerp(__ldg(base + r1 + c1 + zi), fz);

    float3 out;
    out.x = lp(lp(s00.x, s01.x, fy), lp(s10.x, s11.x, fy), fx);
    out.y = lp(lp(s00.y, s01.y, fy), lp(s10.y, s11.y, fy), fx);
    out.z = lp(lp(s00.z, s01.z, fy), lp(s10.z, s11.z, fy), fx);
    return out;
}

__device__ __forceinline__ void store_both(uint2* __restrict__ op,
                                           uint2* __restrict__ os,
                                           int idx, uint2 v) {
    op[idx] = v;
    if (idx > 0) os[idx - 1] = v;   // shifted copy; slot NVOX-1 stays the zero guard
}

// v0 = sign * T[tp] / 2^7 for 8 fields (even f = +, odd f = -)
__global__ void __launch_bounds__(TPB) k_init(const float* __restrict__ T) {
    int idx = blockIdx.x * TPB + threadIdx.x;
    int f = blockIdx.y;
    int tp = f >> 1;
    float s = (f & 1) ? -0.0078125f : 0.0078125f;
    const float* base = T + (size_t)tp * 3 * NVOX;
    uint2 v = packv(s * base[idx], s * base[idx + NVOX], s * base[idx + 2 * NVOX]);
    store_both((uint2*)&g_Ap[f][0], (uint2*)&g_As[f][0], idx, v);
}

// Transpose R (x,y,z,c,p) -> (p,c,voxel) with smem staging for coalesced I/O
__global__ void __launch_bounds__(TPB) k_transpose(const float* __restrict__ R) {
    __shared__ float s[TPB * 18];
    int base = blockIdx.x * TPB;
    for (int j = threadIdx.x; j < TPB * 18; j += TPB)
        s[j] = R[(size_t)base * 18 + j];
    __syncthreads();
    int idx = base + threadIdx.x;
    #pragma unroll
    for (int c = 0; c < 3; c++)
        #pragma unroll
        for (int p = 0; p < NPAIRS; p++)
            g_Rt[p][c][idx] = s[threadIdx.x * 18 + c * 6 + p];
}

// One scaling-and-squaring step for all 8 fields: out = v + sample(v, grid+v)
__global__ void __launch_bounds__(TPB) k_step(int dir) {
    const float4* __restrict__ inp = dir ? &g_Bp[0][0] : &g_Ap[0][0];
    const float4* __restrict__ ins = dir ? &g_Bs[0][0] : &g_As[0][0];
    float4* __restrict__ outp = dir ? &g_Ap[0][0] : &g_Bp[0][0];
    float4* __restrict__ outs = dir ? &g_As[0][0] : &g_Bs[0][0];

    int idx = blockIdx.x * TPB + threadIdx.x;
    int f = blockIdx.y;
    const float4* pp = inp + (size_t)f * NPAIR;
    const float4* sh = ins + (size_t)f * NPAIR;

    float3 v = unpack1(((const uint2*)pp)[idx]);
    int z = idx % NN;
    int t = idx / NN;
    int y = t % NN;
    int x = t / NN;

    float3 s = trisample(pp, sh, (float)x + v.x, (float)y + v.y, (float)z + v.z);
    uint2 o = packv(v.x + s.x, v.y + s.y, v.z + s.z);
    store_both((uint2*)(outp + (size_t)f * NPAIR), (uint2*)(outs + (size_t)f * NPAIR), idx, o);
}

__constant__ int c_ref[NPAIRS] = {0, 0, 0, 1, 1, 2};
__constant__ int c_flo[NPAIRS] = {1, 2, 3, 2, 3, 3};

// Compose + residual norm, block partial sums (results of 7 steps live in g_B*)
__global__ void __launch_bounds__(TPB) k_final() {
    __shared__ double sred[TPB / 32];
    int idx = blockIdx.x * TPB + threadIdx.x;
    int p = blockIdx.y;
    int fn = 2 * c_ref[p] + 1, fp = 2 * c_flo[p];
    const float4* negp = &g_Bp[fn][0];
    const float4* posp = &g_Bp[fp][0];
    const float4* poss = &g_Bs[fp][0];

    float3 v = unpack1(((const uint2*)negp)[idx]);
    int z = idx % NN;
    int t = idx / NN;
    int y = t % NN;
    int x = t / NN;

    float3 s = trisample(posp, poss, (float)x + v.x, (float)y + v.y, (float)z + v.z);
    float rx = v.x + s.x - g_Rt[p][0][idx];
    float ry = v.y + s.y - g_Rt[p][1][idx];
    float rz = v.z + s.z - g_Rt[p][2][idx];
    float term = sqrtf(rx * rx + ry * ry + rz * rz);

    #pragma unroll
    for (int o = 16; o; o >>= 1) term += __shfl_down_sync(0xffffffffu, term, o);

    int lane = threadIdx.x & 31, w = threadIdx.x >> 5;
    if (lane == 0) sred[w] = (double)term;
    __syncthreads();
    if (threadIdx.x == 0) {
        double acc = 0.0;
        #pragma unroll
        for (int i = 0; i < TPB / 32; i++) acc += sred[i];
        g_part[p * NBLK + blockIdx.x] = acc;
    }
}

// Deterministic final reduction of block partials
__global__ void __launch_bounds__(1024) k_reduce(float* __restrict__ out) {
    __shared__ double sred[32];
    double acc = 0.0;
    const int n = NPAIRS * NBLK;
    for (int i = threadIdx.x; i < n; i += 1024) acc += g_part[i];
    #pragma unroll
    for (int o = 16; o; o >>= 1) acc += __shfl_down_sync(0xffffffffu, acc, o);
    int lane = threadIdx.x & 31, w = threadIdx.x >> 5;
    if (lane == 0) sred[w] = acc;
    __syncthreads();
    if (threadIdx.x == 0) {
        double tot = 0.0;
        #pragma unroll
        for (int i = 0; i < 32; i++) tot += sred[i];
        out[0] = (float)tot;
    }
}

extern "C" void kernel_launch(void* const* d_in, const int* in_sizes, int n_in,
                              void* d_out, int out_size) {
    const float* T = (const float*)d_in[0];
    const float* R = (const float*)d_in[1];
    // Robust to metadata ordering: T has 4*3*96^3 = 10,616,832 elems; R has 96^3*18 = 15,925,248
    if (n_in >= 2 && in_sizes[0] == 15925248) {
        T = (const float*)d_in[1];
        R = (const float*)d_in[0];
    }
    float* out = (float*)d_out;

    dim3 blk(TPB);
    dim3 gi(NBLK, NFIELDS);
    k_init<<<gi, blk>>>(T);
    k_transpose<<<NBLK, TPB>>>(R);
    for (int s = 0; s < VSTEPS; s++) {
        k_step<<<gi, blk>>>(s & 1);  // step 0 reads g_A* writes g_B*; alternates; ends in g_B*
    }
    dim3 gf(NBLK, NPAIRS);
    k_final<<<gf, blk>>>();
    k_reduce<<<1, 1024>>>(out);
}

// round 5
// speedup vs baseline: 1.0445x; 1.0445x over previous
#include <cuda_runtime.h>

#define NN 96
#define NVOX 884736        // 96^3
#define NFIELDS 8
#define NPAIRS 6
#define VSTEPS 7
#define TPBL 256           // linear kernels
#define NBLKL (NVOX / TPBL)
#define GBY 48             // grid.x for 3D kernels (y pairs)
#define BLK3 (GBY * NN)    // blocks per field/pair = 4608

// Field voxel = one uint32: x bits[0:11), y bits[11:22), z bits[22:32), signed fixed point.
// Per-step range B_k = 2^k/16; x,y scale 1024/B_k; z scale 512/B_k.
__device__ unsigned g_A[NFIELDS][NVOX];
__device__ unsigned g_B[NFIELDS][NVOX];
__device__ float  g_Rt[NPAIRS][3][NVOX];   // transposed R: (pair, channel, voxel)
__device__ double g_part[NPAIRS * BLK3];

__device__ __forceinline__ float lp(float a, float b, float t) {
    return fmaf(t, b - a, a);
}

// Unpack to UNSCALED floats (ints as floats); caller applies scale.
__device__ __forceinline__ float3 unpack_raw(unsigned u) {
    int ix, iy, iz;
    asm("bfe.s32 %0, %1, 0, 11;"  : "=r"(ix) : "r"(u));
    asm("bfe.s32 %0, %1, 11, 11;" : "=r"(iy) : "r"(u));
    asm("bfe.s32 %0, %1, 22, 10;" : "=r"(iz) : "r"(u));
    return make_float3((float)ix, (float)iy, (float)iz);
}

// fs = 1024/B_out for x,y; z uses fs*0.5 (10 bits)
__device__ __forceinline__ unsigned packv(float x, float y, float z, float fs) {
    int ix = __float2int_rn(fminf(fmaxf(x * fs, -1023.f), 1023.f));
    int iy = __float2int_rn(fminf(fmaxf(y * fs, -1023.f), 1023.f));
    int iz = __float2int_rn(fminf(fmaxf(z * fs * 0.5f, -511.f), 511.f));
    return (unsigned)(ix & 0x7FF) | ((unsigned)(iy & 0x7FF) << 11) | ((unsigned)(iz & 0x3FF) << 22);
}

// Trilinear sample, reference clamp semantics (x0=clip(floor,0,95), x1=clip(x0+1,0,95),
// fractional part NOT clamped). Returns UNSCALED component floats.
__device__ __forceinline__ float3 trisample_raw(const unsigned* __restrict__ vol,
                                                float cx, float cy, float cz) {
    float xf = floorf(cx), yf = floorf(cy), zf = floorf(cz);
    float fx = cx - xf, fy = cy - yf, fz = cz - zf;
    int x0 = min(max((int)xf, 0), NN - 1); int x1 = min(x0 + 1, NN - 1);
    int y0 = min(max((int)yf, 0), NN - 1); int y1 = min(y0 + 1, NN - 1);
    int z0 = min(max((int)zf, 0), NN - 1); int z1 = min(z0 + 1, NN - 1);

    const unsigned* r00 = vol + (x0 * NN + y0) * NN;
    const unsigned* r01 = vol + (x0 * NN + y1) * NN;
    const unsigned* r10 = vol + (x1 * NN + y0) * NN;
    const unsigned* r11 = vol + (x1 * NN + y1) * NN;

    float3 c000 = unpack_raw(__ldg(r00 + z0)), c001 = unpack_raw(__ldg(r00 + z1));
    float3 c010 = unpack_raw(__ldg(r01 + z0)), c011 = unpack_raw(__ldg(r01 + z1));
    float3 c100 = unpack_raw(__ldg(r10 + z0)), c101 = unpack_raw(__ldg(r10 + z1));
    float3 c110 = unpack_raw(__ldg(r11 + z0)), c111 = unpack_raw(__ldg(r11 + z1));

    float3 out;
    {
        float a = lp(c000.x, c001.x, fz), b = lp(c010.x, c011.x, fz);
        float c = lp(c100.x, c101.x, fz), d = lp(c110.x, c111.x, fz);
        out.x = lp(lp(a, b, fy), lp(c, d, fy), fx);
    }
    {
        float a = lp(c000.y, c001.y, fz), b = lp(c010.y, c011.y, fz);
        float c = lp(c100.y, c101.y, fz), d = lp(c110.y, c111.y, fz);
        out.y = lp(lp(a, b, fy), lp(c, d, fy), fx);
    }
    {
        float a = lp(c000.z, c001.z, fz), b = lp(c010.z, c011.z, fz);
        float c = lp(c100.z, c101.z, fz), d = lp(c110.z, c111.z, fz);
        out.z = lp(lp(a, b, fy), lp(c, d, fy), fx);
    }
    return out;
}

// 3D thread mapping: threadIdx.x=z, y = blockIdx.x*2+threadIdx.y, x = blockIdx.y, field/pair = blockIdx.z
// v0 = sign * T[tp] / 2^7; pack at scale fs0 = 16384
__global__ void __launch_bounds__(192) k_init(const float* __restrict__ T) {
    int z = threadIdx.x;
    int y = blockIdx.x * 2 + threadIdx.y;
    int x = blockIdx.y;
    int f = blockIdx.z;
    int idx = (x * NN + y) * NN + z;
    int tp = f >> 1;
    float s = (f & 1) ? -0.0078125f : 0.0078125f;
    const float* base = T + (size_t)tp * 3 * NVOX;
    g_A[f][idx] = packv(s * base[idx], s * base[idx + NVOX], s * base[idx + 2 * NVOX], 16384.f);
}

// Transpose R (x,y,z,c,p) -> (p,c,voxel), smem staged
__global__ void __launch_bounds__(TPBL) k_transpose(const float* __restrict__ R) {
    __shared__ float s[TPBL * 18];
    int base = blockIdx.x * TPBL;
    for (int j = threadIdx.x; j < TPBL * 18; j += TPBL)
        s[j] = R[(size_t)base * 18 + j];
    __syncthreads();
    int idx = base + threadIdx.x;
    #pragma unroll
    for (int c = 0; c < 3; c++)
        #pragma unroll
        for (int p = 0; p < NPAIRS; p++)
            g_Rt[p][c][idx] = s[threadIdx.x * 18 + c * 6 + p];
}

// One squaring step for all 8 fields: out = v + sample(v, grid+v)
// inv_in = B_in/1024 (x,y unscale; z uses 2*inv_in), fs_out = 1024/B_out
__global__ void __launch_bounds__(192) k_step(int dir, float inv_in, float fs_out) {
    const unsigned* __restrict__ inb = dir ? &g_B[0][0] : &g_A[0][0];
    unsigned* __restrict__ outb = dir ? &g_A[0][0] : &g_B[0][0];
    int z = threadIdx.x;
    int y = blockIdx.x * 2 + threadIdx.y;
    int x = blockIdx.y;
    int f = blockIdx.z;
    int idx = (x * NN + y) * NN + z;
    const unsigned* vol = inb + (size_t)f * NVOX;

    float3 vr = unpack_raw(vol[idx]);
    float vx = vr.x * inv_in, vy = vr.y * inv_in, vz = vr.z * (2.f * inv_in);

    float3 sr = trisample_raw(vol, (float)x + vx, (float)y + vy, (float)z + vz);
    float ox = fmaf(sr.x, inv_in, vx);
    float oy = fmaf(sr.y, inv_in, vy);
    float oz = fmaf(sr.z, 2.f * inv_in, vz);
    outb[(size_t)f * NVOX + idx] = packv(ox, oy, oz, fs_out);
}

__constant__ int c_ref[NPAIRS] = {0, 0, 0, 1, 1, 2};
__constant__ int c_flo[NPAIRS] = {1, 2, 3, 2, 3, 3};

// Compose + residual norm; final fields (scale B7=8, inv=1/128) live in g_B
__global__ void __launch_bounds__(192) k_final() {
    __shared__ double sred[6];
    const float inv = 0.0078125f;          // 8/1024
    int z = threadIdx.x;
    int y = blockIdx.x * 2 + threadIdx.y;
    int x = blockIdx.y;
    int p = blockIdx.z;
    int idx = (x * NN + y) * NN + z;
    const unsigned* fneg = &g_B[2 * c_ref[p] + 1][0];
    const unsigned* fpos = &g_B[2 * c_flo[p]][0];

    float3 vr = unpack_raw(fneg[idx]);
    float vx = vr.x * inv, vy = vr.y * inv, vz = vr.z * (2.f * inv);

    float3 sr = trisample_raw(fpos, (float)x + vx, (float)y + vy, (float)z + vz);
    float rx = fmaf(sr.x, inv, vx) - g_Rt[p][0][idx];
    float ry = fmaf(sr.y, inv, vy) - g_Rt[p][1][idx];
    float rz = fmaf(sr.z, 2.f * inv, vz) - g_Rt[p][2][idx];
    float term = sqrtf(rx * rx + ry * ry + rz * rz);

    #pragma unroll
    for (int o = 16; o; o >>= 1) term += __shfl_down_sync(0xffffffffu, term, o);

    int lin = threadIdx.y * NN + threadIdx.x;
    int lane = lin & 31, w = lin >> 5;
    if (lane == 0) sred[w] = (double)term;
    __syncthreads();
    if (lin == 0) {
        double acc = 0.0;
        #pragma unroll
        for (int i = 0; i < 6; i++) acc += sred[i];
        g_part[p * BLK3 + blockIdx.x * NN + blockIdx.y] = acc;
    }
}

// Deterministic final reduction
__global__ void __launch_bounds__(1024) k_reduce(float* __restrict__ out) {
    __shared__ double sred[32];
    double acc = 0.0;
    const int n = NPAIRS * BLK3;
    for (int i = threadIdx.x; i < n; i += 1024) acc += g_part[i];
    #pragma unroll
    for (int o = 16; o; o >>= 1) acc += __shfl_down_sync(0xffffffffu, acc, o);
    int lane = threadIdx.x & 31, w = threadIdx.x >> 5;
    if (lane == 0) sred[w] = acc;
    __syncthreads();
    if (threadIdx.x == 0) {
        double tot = 0.0;
        #pragma unroll
        for (int i = 0; i < 32; i++) tot += sred[i];
        out[0] = (float)tot;
    }
}

extern "C" void kernel_launch(void* const* d_in, const int* in_sizes, int n_in,
                              void* d_out, int out_size) {
    const float* T = (const float*)d_in[0];
    const float* R = (const float*)d_in[1];
    if (n_in >= 2 && in_sizes[0] == 15925248) {   // robust to metadata ordering
        T = (const float*)d_in[1];
        R = (const float*)d_in[0];
    }
    float* out = (float*)d_out;

    dim3 blk(NN, 2);
    dim3 gi(GBY, NN, NFIELDS);
    k_init<<<gi, blk>>>(T);
    k_transpose<<<NBLKL, TPBL>>>(R);
    for (int s = 0; s < VSTEPS; s++) {
        // input scale B_s = 2^s/16 -> inv_in = B_s/1024 = 2^s/16384
        // output scale fs_out = 1024/B_{s+1} = 16384/2^(s+1)
        float inv_in = ldexpf(1.f, s - 14);
        float fs_out = ldexpf(1.f, 13 - s);
        k_step<<<gi, blk>>>(s & 1, inv_in, fs_out);   // ends in g_B after 7 steps
    }
    dim3 gf(GBY, NN, NPAIRS);
    k_final<<<gf, blk>>>();
    k_reduce<<<1, 1024>>>(out);
}

// round 7
// speedup vs baseline: 1.0561x; 1.0111x over previous
#include <cuda_runtime.h>

#define NN 96
#define NVOX 884736        // 96^3
#define NFIELDS 8
#define NPAIRS 6
#define VSTEPS 7
#define TPBL 256           // linear kernels
#define NBLKL (NVOX / TPBL)
#define GBY 48             // grid.x for 3D kernels (y pairs)
#define BLK3 (GBY * NN)    // blocks per field/pair = 4608

// Field voxel = one uint32, BIASED unsigned fields:
//   bits[0:11)  px = ix + 1024   (x, scale 1024/B_k)
//   bits[11:22) py = iy + 1024   (y, scale 1024/B_k)
//   bits[22:32) pz = iz + 512    (z, scale 512/B_k)
// Per-step range B_k = 2^k/16 (powers of two -> all scale math exact).
__device__ unsigned g_A[NFIELDS][NVOX];
__device__ unsigned g_B[NFIELDS][NVOX];
__device__ float  g_Rt[NPAIRS][3][NVOX];   // transposed R: (pair, channel, voxel)
__device__ double g_part[NPAIRS * BLK3];

#define MAGIC_I   0x4B000000u          // 2^23 as float bits (OR-able with 11-bit payload)
#define CXY       8389632.f            // 2^23 + 1024
#define CZ        8389120.f            // 2^23 + 512
#define FMAGIC    12582912.f           // 1.5 * 2^23
#define FMAGIC_I  0x4B400000

__device__ __forceinline__ float lp(float a, float b, float t) {
    return fmaf(t, b - a, a);
}

// z-lerp with bias removal folded in: (a - C) + fz*(b - a); biases of a,b cancel in diff
__device__ __forceinline__ float zl(float a, float b, float fz, float C) {
    return fmaf(fz, b - a, a - C);
}

// round-toward-minus-inf add (for magic floor)
__device__ __forceinline__ float fadd_rm(float a, float b) {
    float r;
    asm("add.rm.f32 %0, %1, %2;" : "=f"(r) : "f"(a), "f"(b));
    return r;
}

// Magic floor: returns integer floor in *xi, float frac (cx - floor(cx)), no CVT ops.
__device__ __forceinline__ float mfloor(float cx, int* xi) {
    float t = fadd_rm(cx, FMAGIC);                 // mantissa = floor(cx)
    *xi = __float_as_int(t) - FMAGIC_I;
    return cx - (t - FMAGIC);                      // exact frac
}

// Magic pack of one component: clamp, round-to-nearest, bias. lim=1023 bias=1024 (x,y); 511/512 (z)
__device__ __forceinline__ int mpack(float v, float lim, int bias) {
    float c = fminf(fmaxf(v, -lim), lim) + FMAGIC; // RN add -> nearest int in mantissa
    return __float_as_int(c) - FMAGIC_I + bias;
}

__device__ __forceinline__ unsigned packv(float x, float y, float z, float fs) {
    int px = mpack(x * fs,        1023.f, 1024);
    int py = mpack(y * fs,        1023.f, 1024);
    int pz = mpack(z * fs * 0.5f, 511.f,  512);
    return (unsigned)(px + (py << 11) + (pz << 22));
}

// Magic corner decode: biased floats 2^23 + p*
__device__ __forceinline__ float3 mdec(unsigned u) {
    float3 m;
    m.x = __int_as_float((u & 0x7FFu) | MAGIC_I);
    m.y = __int_as_float(((u >> 11) & 0x7FFu) | MAGIC_I);
    m.z = __int_as_float((u >> 22) | MAGIC_I);
    return m;
}

// Trilinear sample, reference clamp semantics (x0=clip(floor,0,95), x1=clip(x0+1,0,95),
// fractional part NOT clamped). Returns UNSCALED signed fixed-point floats (ix units).
__device__ __forceinline__ float3 trisample_raw(const unsigned* __restrict__ vol,
                                                float cx, float cy, float cz) {
    int xi, yi, zi;
    float fx = mfloor(cx, &xi);
    float fy = mfloor(cy, &yi);
    float fz = mfloor(cz, &zi);
    int x0 = min(max(xi, 0), NN - 1); int x1 = min(x0 + 1, NN - 1);
    int y0 = min(max(yi, 0), NN - 1); int y1 = min(y0 + 1, NN - 1);
    int z0 = min(max(zi, 0), NN - 1); int z1 = min(z0 + 1, NN - 1);

    const unsigned* r00 = vol + (x0 * NN + y0) * NN;
    const unsigned* r01 = vol + (x0 * NN + y1) * NN;
    const unsigned* r10 = vol + (x1 * NN + y0) * NN;
    const unsigned* r11 = vol + (x1 * NN + y1) * NN;

    float3 c000 = mdec(__ldg(r00 + z0)), c001 = mdec(__ldg(r00 + z1));
    float3 c010 = mdec(__ldg(r01 + z0)), c011 = mdec(__ldg(r01 + z1));
    float3 c100 = mdec(__ldg(r10 + z0)), c101 = mdec(__ldg(r10 + z1));
    float3 c110 = mdec(__ldg(r11 + z0)), c111 = mdec(__ldg(r11 + z1));

    float3 out;
    {   // x component (bias CXY removed in z-lerp)
        float a = zl(c000.x, c001.x, fz, CXY), b = zl(c010.x, c011.x, fz, CXY);
        float c = zl(c100.x, c101.x, fz, CXY), d = zl(c110.x, c111.x, fz, CXY);
        out.x = lp(lp(a, b, fy), lp(c, d, fy), fx);
    }
    {   // y component
        float a = zl(c000.y, c001.y, fz, CXY), b = zl(c010.y, c011.y, fz, CXY);
        float c = zl(c100.y, c101.y, fz, CXY), d = zl(c110.y, c111.y, fz, CXY);
        out.y = lp(lp(a, b, fy), lp(c, d, fy), fx);
    }
    {   // z component (bias CZ)
        float a = zl(c000.z, c001.z, fz, CZ), b = zl(c010.z, c011.z, fz, CZ);
        float c = zl(c100.z, c101.z, fz, CZ), d = zl(c110.z, c111.z, fz, CZ);
        out.z = lp(lp(a, b, fy), lp(c, d, fy), fx);
    }
    return out;
}

// 3D thread mapping: threadIdx.x=z, y = blockIdx.x*2+threadIdx.y, x = blockIdx.y, field = blockIdx.z
__global__ void __launch_bounds__(192) k_init(const float* __restrict__ T) {
    int z = threadIdx.x;
    int y = blockIdx.x * 2 + threadIdx.y;
    int x = blockIdx.y;
    int f = blockIdx.z;
    int idx = (x * NN + y) * NN + z;
    int tp = f >> 1;
    float s = (f & 1) ? -0.0078125f : 0.0078125f;
    const float* base = T + (size_t)tp * 3 * NVOX;
    g_A[f][idx] = packv(s * base[idx], s * base[idx + NVOX], s * base[idx + 2 * NVOX], 16384.f);
}

// Transpose R (x,y,z,c,p) -> (p,c,voxel), smem staged
__global__ void __launch_bounds__(TPBL) k_transpose(const float* __restrict__ R) {
    __shared__ float s[TPBL * 18];
    int base = blockIdx.x * TPBL;
    for (int j = threadIdx.x; j < TPBL * 18; j += TPBL)
        s[j] = R[(size_t)base * 18 + j];
    __syncthreads();
    int idx = base + threadIdx.x;
    #pragma unroll
    for (int c = 0; c < 3; c++)
        #pragma unroll
        for (int p = 0; p < NPAIRS; p++)
            g_Rt[p][c][idx] = s[threadIdx.x * 18 + c * 6 + p];
}

// One squaring step for all 8 fields: out = v + sample(v, grid+v)
// inv  = B_in/1024 (x,y unscale), inv2 = 2*inv (z); oxy = -CXY*inv, oz = -CZ*inv2 (exact)
__global__ void __launch_bounds__(192) k_step(int dir, float inv, float inv2,
                                              float oxy, float oz, float fs_out) {
    const unsigned* __restrict__ inb = dir ? &g_B[0][0] : &g_A[0][0];
    unsigned* __restrict__ outb = dir ? &g_A[0][0] : &g_B[0][0];
    int z = threadIdx.x;
    int y = blockIdx.x * 2 + threadIdx.y;
    int x = blockIdx.y;
    int f = blockIdx.z;
    int idx = (x * NN + y) * NN + z;
    const unsigned* vol = inb + (size_t)f * NVOX;

    float3 m = mdec(vol[idx]);
    float vx = fmaf(m.x, inv, oxy);    // exact: inv is a power of two
    float vy = fmaf(m.y, inv, oxy);
    float vz = fmaf(m.z, inv2, oz);

    float3 sr = trisample_raw(vol, (float)x + vx, (float)y + vy, (float)z + vz);
    float ox = fmaf(sr.x, inv, vx);
    float oy = fmaf(sr.y, inv, vy);
    float oz2 = fmaf(sr.z, inv2, vz);
    outb[(size_t)f * NVOX + idx] = packv(ox, oy, oz2, fs_out);
}

__constant__ int c_ref[NPAIRS] = {0, 0, 0, 1, 1, 2};
__constant__ int c_flo[NPAIRS] = {1, 2, 3, 2, 3, 3};

// Compose + residual norm; final fields (scale B7=8 -> inv=1/128) live in g_B
__global__ void __launch_bounds__(192) k_final() {
    __shared__ double sred[6];
    const float inv  = 0.0078125f;            // 1/128
    const float inv2 = 0.015625f;             // 1/64
    const float oxy  = -CXY * 0.0078125f;
    const float ozc  = -CZ * 0.015625f;
    int z = threadIdx.x;
    int y = blockIdx.x * 2 + threadIdx.y;
    int x = blockIdx.y;
    int p = blockIdx.z;
    int idx = (x * NN + y) * NN + z;
    const unsigned* fneg = &g_B[2 * c_ref[p] + 1][0];
    const unsigned* fpos = &g_B[2 * c_flo[p]][0];

    float3 m = mdec(fneg[idx]);
    float vx = fmaf(m.x, inv, oxy);
    float vy = fmaf(m.y, inv, oxy);
    float vz = fmaf(m.z, inv2, ozc);

    float3 sr = trisample_raw(fpos, (float)x + vx, (float)y + vy, (float)z + vz);
    float rx = fmaf(sr.x, inv, vx) - g_Rt[p][0][idx];
    float ry = fmaf(sr.y, inv, vy) - g_Rt[p][1][idx];
    float rz = fmaf(sr.z, inv2, vz) - g_Rt[p][2][idx];
    float term = sqrtf(rx * rx + ry * ry + rz * rz);

    #pragma unroll
    for (int o = 16; o; o >>= 1) term += __shfl_down_sync(0xffffffffu, term, o);

    int lin = threadIdx.y * NN + threadIdx.x;
    int lane = lin & 31, w = lin >> 5;
    if (lane == 0) sred[w] = (double)term;
    __syncthreads();
    if (lin == 0) {
        double acc = 0.0;
        #pragma unroll
        for (int i = 0; i < 6; i++) acc += sred[i];
        g_part[p * BLK3 + blockIdx.x * NN + blockIdx.y] = acc;
    }
}

// Deterministic final reduction
__global__ void __launch_bounds__(1024) k_reduce(float* __restrict__ out) {
    __shared__ double sred[32];
    double acc = 0.0;
    const int n = NPAIRS * BLK3;
    for (int i = threadIdx.x; i < n; i += 1024) acc += g_part[i];
    #pragma unroll
    for (int o = 16; o; o >>= 1) acc += __shfl_down_sync(0xffffffffu, acc, o);
    int lane = threadIdx.x & 31, w = threadIdx.x >> 5;
    if (lane == 0) sred[w] = acc;
    __syncthreads();
    if (threadIdx.x == 0) {
        double tot = 0.0;
        #pragma unroll
        for (int i = 0; i < 32; i++) tot += sred[i];
        out[0] = (float)tot;
    }
}

extern "C" void kernel_launch(void* const* d_in, const int* in_sizes, int n_in,
                              void* d_out, int out_size) {
    const float* T = (const float*)d_in[0];
    const float* R = (const float*)d_in[1];
    if (n_in >= 2 && in_sizes[0] == 15925248) {   // robust to metadata ordering
        T = (const float*)d_in[1];
        R = (const float*)d_in[0];
    }
    float* out = (float*)d_out;

    dim3 blk(NN, 2);
    dim3 gi(GBY, NN, NFIELDS);
    k_init<<<gi, blk>>>(T);
    k_transpose<<<NBLKL, TPBL>>>(R);
    for (int s = 0; s < VSTEPS; s++) {
        float inv  = ldexpf(1.f, s - 14);      // B_s/1024 = 2^(s-14)
        float inv2 = ldexpf(1.f, s - 13);
        float oxy  = -CXY * inv;               // exact (power-of-two scale)
        float oz   = -CZ * inv2;
        float fs_o = ldexpf(1.f, 13 - s);      // 1024/B_{s+1}
        k_step<<<gi, blk>>>(s & 1, inv, inv2, oxy, oz, fs_o);  // ends in g_B
    }
    dim3 gf(GBY, NN, NPAIRS);
    k_final<<<gf, blk>>>();
    k_reduce<<<1, 1024>>>(out);
}

// round 8
// speedup vs baseline: 1.3746x; 1.3015x over previous
#include <cuda_runtime.h>

#define NN 96
#define NVOX 884736        // 96^3
#define NFIELDS 6          // only fields the loss consumes: neg0,pos1,neg1,pos2,neg2,pos3
#define NPAIRS 6
#define VSTEPS 7
#define TPBL 256           // linear kernels
#define NBLKL (NVOX / TPBL)
#define BLK3 (48 * NN)     // k_final blocks per pair = 4608

// Field voxel = one uint32, BIASED unsigned fields:
//   bits[0:11)  px = ix + 1024   (x, scale 1024/B_k)
//   bits[11:22) py = iy + 1024   (y, scale 1024/B_k)
//   bits[22:32) pz = iz + 512    (z, scale 512/B_k)
// Per-step range B_k = 2^k/16 (powers of two -> all scale math exact).
__device__ __align__(16) unsigned g_A[NFIELDS][NVOX];
__device__ __align__(16) unsigned g_B[NFIELDS][NVOX];
__device__ float  g_Rt[NPAIRS][3][NVOX];   // transposed R: (pair, channel, voxel)
__device__ double g_part[NPAIRS * BLK3];

#define MAGIC_I   0x4B000000u          // 2^23 as float bits (OR-able with 11-bit payload)
#define CXY       8389632.f            // 2^23 + 1024
#define CZ        8389120.f            // 2^23 + 512
#define FMAGIC    12582912.f           // 1.5 * 2^23
#define FMAGIC_I  0x4B400000

__device__ __forceinline__ float lp(float a, float b, float t) {
    return fmaf(t, b - a, a);
}

// z-lerp with bias removal folded in: (a - C) + fz*(b - a); biases of a,b cancel in diff
__device__ __forceinline__ float zl(float a, float b, float fz, float C) {
    return fmaf(fz, b - a, a - C);
}

// round-toward-minus-inf add (for magic floor)
__device__ __forceinline__ float fadd_rm(float a, float b) {
    float r;
    asm("add.rm.f32 %0, %1, %2;" : "=f"(r) : "f"(a), "f"(b));
    return r;
}

// Magic floor: returns integer floor in *xi, float frac (cx - floor(cx)), no CVT ops.
__device__ __forceinline__ float mfloor(float cx, int* xi) {
    float t = fadd_rm(cx, FMAGIC);                 // mantissa = floor(cx)
    *xi = __float_as_int(t) - FMAGIC_I;
    return cx - (t - FMAGIC);                      // exact frac
}

// Magic pack of one component: clamp, round-to-nearest, bias.
__device__ __forceinline__ int mpack(float v, float lim, int bias) {
    float c = fminf(fmaxf(v, -lim), lim) + FMAGIC; // RN add -> nearest int in mantissa
    return __float_as_int(c) - FMAGIC_I + bias;
}

__device__ __forceinline__ unsigned packv(float x, float y, float z, float fs) {
    int px = mpack(x * fs,        1023.f, 1024);
    int py = mpack(y * fs,        1023.f, 1024);
    int pz = mpack(z * fs * 0.5f, 511.f,  512);
    return (unsigned)(px + (py << 11) + (pz << 22));
}

// Magic corner decode: biased floats 2^23 + p*
__device__ __forceinline__ float3 mdec(unsigned u) {
    float3 m;
    m.x = __int_as_float((u & 0x7FFu) | MAGIC_I);
    m.y = __int_as_float(((u >> 11) & 0x7FFu) | MAGIC_I);
    m.z = __int_as_float((u >> 22) | MAGIC_I);
    return m;
}

// Trilinear sample, reference clamp semantics (x0=clip(floor,0,95), x1=clip(x0+1,0,95),
// fractional part NOT clamped). Returns UNSCALED signed fixed-point floats (ix units).
__device__ __forceinline__ float3 trisample_raw(const unsigned* __restrict__ vol,
                                                float cx, float cy, float cz) {
    int xi, yi, zi;
    float fx = mfloor(cx, &xi);
    float fy = mfloor(cy, &yi);
    float fz = mfloor(cz, &zi);
    int x0 = min(max(xi, 0), NN - 1); int x1 = min(x0 + 1, NN - 1);
    int y0 = min(max(yi, 0), NN - 1); int y1 = min(y0 + 1, NN - 1);
    int z0 = min(max(zi, 0), NN - 1); int z1 = min(z0 + 1, NN - 1);

    const unsigned* r00 = vol + (x0 * NN + y0) * NN;
    const unsigned* r01 = vol + (x0 * NN + y1) * NN;
    const unsigned* r10 = vol + (x1 * NN + y0) * NN;
    const unsigned* r11 = vol + (x1 * NN + y1) * NN;

    float3 c000 = mdec(__ldg(r00 + z0)), c001 = mdec(__ldg(r00 + z1));
    float3 c010 = mdec(__ldg(r01 + z0)), c011 = mdec(__ldg(r01 + z1));
    float3 c100 = mdec(__ldg(r10 + z0)), c101 = mdec(__ldg(r10 + z1));
    float3 c110 = mdec(__ldg(r11 + z0)), c111 = mdec(__ldg(r11 + z1));

    float3 out;
    {   // x component (bias CXY removed in z-lerp)
        float a = zl(c000.x, c001.x, fz, CXY), b = zl(c010.x, c011.x, fz, CXY);
        float c = zl(c100.x, c101.x, fz, CXY), d = zl(c110.x, c111.x, fz, CXY);
        out.x = lp(lp(a, b, fy), lp(c, d, fy), fx);
    }
    {   // y component
        float a = zl(c000.y, c001.y, fz, CXY), b = zl(c010.y, c011.y, fz, CXY);
        float c = zl(c100.y, c101.y, fz, CXY), d = zl(c110.y, c111.y, fz, CXY);
        out.y = lp(lp(a, b, fy), lp(c, d, fy), fx);
    }
    {   // z component (bias CZ)
        float a = zl(c000.z, c001.z, fz, CZ), b = zl(c010.z, c011.z, fz, CZ);
        float c = zl(c100.z, c101.z, fz, CZ), d = zl(c110.z, c111.z, fz, CZ);
        out.z = lp(lp(a, b, fy), lp(c, d, fy), fx);
    }
    return out;
}

// Field table: f -> transform index; sign = (f odd) ? + : -
// 0:neg T0, 1:pos T1, 2:neg T1, 3:pos T2, 4:neg T2, 5:pos T3
__constant__ int c_ftp[NFIELDS] = {0, 1, 1, 2, 2, 3};

// k_init: threadIdx.x=z(96), y = blockIdx.x*2+threadIdx.y, x = blockIdx.y, field = blockIdx.z
__global__ void __launch_bounds__(192) k_init(const float* __restrict__ T) {
    int z = threadIdx.x;
    int y = blockIdx.x * 2 + threadIdx.y;
    int x = blockIdx.y;
    int f = blockIdx.z;
    int idx = (x * NN + y) * NN + z;
    int tp = c_ftp[f];
    float s = (f & 1) ? 0.0078125f : -0.0078125f;
    const float* base = T + (size_t)tp * 3 * NVOX;
    g_A[f][idx] = packv(s * base[idx], s * base[idx + NVOX], s * base[idx + 2 * NVOX], 16384.f);
}

// Transpose R (x,y,z,c,p) -> (p,c,voxel), smem staged
__global__ void __launch_bounds__(TPBL) k_transpose(const float* __restrict__ R) {
    __shared__ float s[TPBL * 18];
    int base = blockIdx.x * TPBL;
    for (int j = threadIdx.x; j < TPBL * 18; j += TPBL)
        s[j] = R[(size_t)base * 18 + j];
    __syncthreads();
    int idx = base + threadIdx.x;
    #pragma unroll
    for (int c = 0; c < 3; c++)
        #pragma unroll
        for (int p = 0; p < NPAIRS; p++)
            g_Rt[p][c][idx] = s[threadIdx.x * 18 + c * 6 + p];
}

// One squaring step, 6 fields, TWO z-voxels per thread (even/odd pair).
// threadIdx.x = z-pair (48), threadIdx.y covers 4 y rows; grid (24, 96, 6).
// inv = B_in/1024 (x,y unscale), inv2 = 2*inv (z); oxy = -CXY*inv, ozc = -CZ*inv2 (exact)
__global__ void __launch_bounds__(192) k_step(int dir, float inv, float inv2,
                                              float oxy, float ozc, float fs_out) {
    const unsigned* __restrict__ inb = dir ? &g_B[0][0] : &g_A[0][0];
    unsigned* __restrict__ outb = dir ? &g_A[0][0] : &g_B[0][0];
    int z0 = threadIdx.x * 2;
    int y = blockIdx.x * 4 + threadIdx.y;
    int x = blockIdx.y;
    int f = blockIdx.z;
    int idx = (x * NN + y) * NN + z0;
    const unsigned* vol = inb + (size_t)f * NVOX;

    uint2 cc = *reinterpret_cast<const uint2*>(vol + idx);
    float fx_ = (float)x, fy_ = (float)y, fz_ = (float)z0;
    uint2 oo;

    {   // voxel z0
        float3 m = mdec(cc.x);
        float vx = fmaf(m.x, inv, oxy);
        float vy = fmaf(m.y, inv, oxy);
        float vz = fmaf(m.z, inv2, ozc);
        float3 sr = trisample_raw(vol, fx_ + vx, fy_ + vy, fz_ + vz);
        oo.x = packv(fmaf(sr.x, inv, vx), fmaf(sr.y, inv, vy), fmaf(sr.z, inv2, vz), fs_out);
    }
    {   // voxel z0+1
        float3 m = mdec(cc.y);
        float vx = fmaf(m.x, inv, oxy);
        float vy = fmaf(m.y, inv, oxy);
        float vz = fmaf(m.z, inv2, ozc);
        float3 sr = trisample_raw(vol, fx_ + vx, fy_ + vy, (fz_ + 1.f) + vz);
        oo.y = packv(fmaf(sr.x, inv, vx), fmaf(sr.y, inv, vy), fmaf(sr.z, inv2, vz), fs_out);
    }
    *reinterpret_cast<uint2*>(outb + (size_t)f * NVOX + idx) = oo;
}

// Per-pair field ids: fneg = map_neg[REF_IDX[p]] ({0,1,2}->{0,2,4}),
//                     fpos = map_pos[FLO_IDX[p]] ({1,2,3}->{1,3,5})
__constant__ int c_fn[NPAIRS] = {0, 0, 0, 2, 2, 4};
__constant__ int c_fp[NPAIRS] = {1, 3, 5, 3, 5, 5};

// Compose + residual norm; final fields (scale B7=8 -> inv=1/128) live in g_B
__global__ void __launch_bounds__(192) k_final() {
    __shared__ double sred[6];
    const float inv  = 0.0078125f;            // 1/128
    const float inv2 = 0.015625f;             // 1/64
    const float oxy  = -CXY * 0.0078125f;
    const float ozc  = -CZ * 0.015625f;
    int z = threadIdx.x;
    int y = blockIdx.x * 2 + threadIdx.y;
    int x = blockIdx.y;
    int p = blockIdx.z;
    int idx = (x * NN + y) * NN + z;
    const unsigned* fneg = &g_B[c_fn[p]][0];
    const unsigned* fpos = &g_B[c_fp[p]][0];

    float3 m = mdec(fneg[idx]);
    float vx = fmaf(m.x, inv, oxy);
    float vy = fmaf(m.y, inv, oxy);
    float vz = fmaf(m.z, inv2, ozc);

    float3 sr = trisample_raw(fpos, (float)x + vx, (float)y + vy, (float)z + vz);
    float rx = fmaf(sr.x, inv, vx) - g_Rt[p][0][idx];
    float ry = fmaf(sr.y, inv, vy) - g_Rt[p][1][idx];
    float rz = fmaf(sr.z, inv2, vz) - g_Rt[p][2][idx];
    float term = sqrtf(rx * rx + ry * ry + rz * rz);

    #pragma unroll
    for (int o = 16; o; o >>= 1) term += __shfl_down_sync(0xffffffffu, term, o);

    int lin = threadIdx.y * NN + threadIdx.x;
    int lane = lin & 31, w = lin >> 5;
    if (lane == 0) sred[w] = (double)term;
    __syncthreads();
    if (lin == 0) {
        double acc = 0.0;
        #pragma unroll
        for (int i = 0; i < 6; i++) acc += sred[i];
        g_part[p * BLK3 + blockIdx.x * NN + blockIdx.y] = acc;
    }
}

// Deterministic final reduction
__global__ void __launch_bounds__(1024) k_reduce(float* __restrict__ out) {
    __shared__ double sred[32];
    double acc = 0.0;
    const int n = NPAIRS * BLK3;
    for (int i = threadIdx.x; i < n; i += 1024) acc += g_part[i];
    #pragma unroll
    for (int o = 16; o; o >>= 1) acc += __shfl_down_sync(0xffffffffu, acc, o);
    int lane = threadIdx.x & 31, w = threadIdx.x >> 5;
    if (lane == 0) sred[w] = acc;
    __syncthreads();
    if (threadIdx.x == 0) {
        double tot = 0.0;
        #pragma unroll
        for (int i = 0; i < 32; i++) tot += sred[i];
        out[0] = (float)tot;
    }
}

extern "C" void kernel_launch(void* const* d_in, const int* in_sizes, int n_in,
                              void* d_out, int out_size) {
    const float* T = (const float*)d_in[0];
    const float* R = (const float*)d_in[1];
    if (n_in >= 2 && in_sizes[0] == 15925248) {   // robust to metadata ordering
        T = (const float*)d_in[1];
        R = (const float*)d_in[0];
    }
    float* out = (float*)d_out;

    dim3 bi(NN, 2);
    dim3 gi(48, NN, NFIELDS);
    k_init<<<gi, bi>>>(T);
    k_transpose<<<NBLKL, TPBL>>>(R);

    dim3 bs(48, 4);
    dim3 gs(24, NN, NFIELDS);
    for (int s = 0; s < VSTEPS; s++) {
        float inv  = ldexpf(1.f, s - 14);      // B_s/1024 = 2^(s-14)
        float inv2 = ldexpf(1.f, s - 13);
        float oxy  = -CXY * inv;               // exact (power-of-two scale)
        float oz   = -CZ * inv2;
        float fs_o = ldexpf(1.f, 13 - s);      // 1024/B_{s+1}
        k_step<<<gs, bs>>>(s & 1, inv, inv2, oxy, oz, fs_o);  // ends in g_B
    }
    dim3 gf(48, NN, NPAIRS);
    k_final<<<gf, bi>>>();
    k_reduce<<<1, 1024>>>(out);
}

// round 10
// speedup vs baseline: 1.7151x; 1.2477x over previous
#include <cuda_runtime.h>

#define NN 96
#define NP 9216            // 96*96
#define NVOX 884736        // 96^3
#define NFIELDS 6          // fields the loss consumes: neg0,pos1,neg1,pos2,neg2,pos3
#define NFA 7              // +1 zero dummy field: OOB landing zone for weight-0 reads
#define NPAIRS 6
#define VSTEPS 7
#define TPBL 256
#define NBLKL (NVOX / TPBL)
#define BLK3 (48 * NN)     // k_final partial blocks per ref

// Field voxel = one uint32, biased unsigned fields:
//   bits[0:11)  px = ix + 1024, bits[11:22) py = iy + 1024, bits[22:32) pz = iz + 512
// Per-step range B_k = 2^k/16 (powers of two -> all scale folds exact).
__device__ __align__(16) unsigned g_A[NFA][NVOX];
__device__ __align__(16) unsigned g_B[NFA][NVOX];
__device__ float  g_Rt[3][NPAIRS][NVOX];   // transposed R + debias fold, [chan][pair][voxel]
__device__ double g_part[3 * BLK3];

#define MAGIC_I   0x4B000000u          // 2^23 float bits
#define FMAGIC    12582912.f           // 1.5 * 2^23
#define FMAGIC_I  0x4B400000

__device__ __forceinline__ float lp(float a, float b, float t) {
    return fmaf(t, b - a, a);
}

__device__ __forceinline__ float fadd_rm(float a, float b) {
    float r;
    asm("add.rm.f32 %0, %1, %2;" : "=f"(r) : "f"(a), "f"(b));
    return r;
}

// corner decodes -> biased floats 2^23 + p
__device__ __forceinline__ float dcx(unsigned u) { return __int_as_float((u & 0x7FFu) | MAGIC_I); }
__device__ __forceinline__ float dcy(unsigned u) { return __int_as_float(((u >> 11) & 0x7FFu) | MAGIC_I); }
__device__ __forceinline__ float dcz(unsigned u) { return __int_as_float((u >> 22) | MAGIC_I); }

// Sample setup: global floor via folded magic (xm = float(FMAGIC+x)), fracs,
// reference clamp semantics: x0=clip(floor,0,95); HIGH side (floor>=95) kills frac
// (x1==x0 in reference -> frac weight irrelevant); low side keeps frac (x0=0,x1=1).
__device__ __forceinline__ void setup(float vx, float vy, float vz,
                                      float xm, float ym, float zm,
                                      int* off, float* fx, float* fy, float* fz) {
    float t;
    t = fadd_rm(vx, xm); int xi = __float_as_int(t) - FMAGIC_I; *fx = vx - (t - xm);
    t = fadd_rm(vy, ym); int yi = __float_as_int(t) - FMAGIC_I; *fy = vy - (t - ym);
    t = fadd_rm(vz, zm); int zi = __float_as_int(t) - FMAGIC_I; *fz = vz - (t - zm);
    if (xi >= NN - 1) *fx = 0.f;
    if (yi >= NN - 1) *fy = 0.f;
    if (zi >= NN - 1) *fz = 0.f;
    int x0 = min(max(xi, 0), NN - 1);
    int y0 = min(max(yi, 0), NN - 1);
    int z0 = min(max(zi, 0), NN - 1);
    *off = (x0 * NN + y0) * NN + z0;
}

// Fetch 8 corners from single base + immediate offsets, lerp biased floats.
// Returns (wx,wy,wz) = 2^23 + lerped biased fixed-point values.
__device__ __forceinline__ float3 fetchlerp(const unsigned* __restrict__ p,
                                            float fx, float fy, float fz) {
    unsigned uA = __ldg(p),           uB = __ldg(p + 1);
    unsigned uC = __ldg(p + NN),      uD = __ldg(p + NN + 1);
    unsigned uE = __ldg(p + NP),      uF = __ldg(p + NP + 1);
    unsigned uG = __ldg(p + NP + NN), uH = __ldg(p + NP + NN + 1);

    float3 w;
    {
        float a = lp(dcx(uA), dcx(uB), fz), b = lp(dcx(uC), dcx(uD), fz);
        float c = lp(dcx(uE), dcx(uF), fz), d = lp(dcx(uG), dcx(uH), fz);
        w.x = lp(lp(a, b, fy), lp(c, d, fy), fx);
    }
    {
        float a = lp(dcy(uA), dcy(uB), fz), b = lp(dcy(uC), dcy(uD), fz);
        float c = lp(dcy(uE), dcy(uF), fz), d = lp(dcy(uG), dcy(uH), fz);
        w.y = lp(lp(a, b, fy), lp(c, d, fy), fx);
    }
    {
        float a = lp(dcz(uA), dcz(uB), fz), b = lp(dcz(uC), dcz(uD), fz);
        float c = lp(dcz(uE), dcz(uF), fz), d = lp(dcz(uG), dcz(uH), fz);
        w.z = lp(lp(a, b, fy), lp(c, d, fy), fx);
    }
    return w;
}

// round-to-nearest with bias folded into the int subtract
__device__ __forceinline__ int cpack(float t, float lo, float hi, int bias) {
    float c = fminf(fmaxf(t, lo), hi) + FMAGIC;
    return __float_as_int(c) - (FMAGIC_I - bias);
}

// Field table: f -> transform index; sign = (f odd) ? + : -
// 0:neg T0, 1:pos T1, 2:neg T1, 3:pos T2, 4:neg T2, 5:pos T3
__constant__ int c_ftp[NFIELDS] = {0, 1, 1, 2, 2, 3};

__global__ void __launch_bounds__(192) k_init(const float* __restrict__ T) {
    int z = threadIdx.x;
    int y = blockIdx.x * 2 + threadIdx.y;
    int x = blockIdx.y;
    int f = blockIdx.z;
    int idx = (x * NN + y) * NN + z;
    int tp = c_ftp[f];
    float s = (f & 1) ? 0.0078125f : -0.0078125f;
    const float* base = T + (size_t)tp * 3 * NVOX;
    int px = cpack(s * base[idx]            * 16384.f, -1023.f, 1023.f, 1024);
    int py = cpack(s * base[idx + NVOX]     * 16384.f, -1023.f, 1023.f, 1024);
    int pz = cpack(s * base[idx + 2 * NVOX] * 8192.f,  -511.f,  511.f,  512);
    g_A[f][idx] = (unsigned)(px + (py << 11) + (pz << 22));
}

// Transpose R (x,y,z,c,p) -> (c,p,voxel); fold debias consts (exact to 2 mantissa bits)
__global__ void __launch_bounds__(TPBL) k_transpose(const float* __restrict__ R) {
    __shared__ float s[TPBL * 18];
    int base = blockIdx.x * TPBL;
    for (int j = threadIdx.x; j < TPBL * 18; j += TPBL)
        s[j] = R[(size_t)base * 18 + j];
    __syncthreads();
    int idx = base + threadIdx.x;
    #pragma unroll
    for (int c = 0; c < 3; c++) {
        float fold = (c == 2) ? 131080.f : 65544.f;   // (2^23+512)/64, (2^23+1024)/128
        #pragma unroll
        for (int p = 0; p < NPAIRS; p++)
            g_Rt[c][p][idx] = s[threadIdx.x * 18 + c * 6 + p] + fold;
    }
}

// One squaring step, 6 fields, two z-voxels per thread.
// inv=2^(s-14), inv2=2^(s-13); co_x=-(2^23+1024)*inv, co_z=-(2^23+512)*inv2 (exact);
// fs=2^(13-s), fsz=2^(12-s) with inv*fs = inv2*fsz = 0.5.
__global__ void __launch_bounds__(192) k_step(int dir, float inv, float inv2,
                                              float co_x, float co_z,
                                              float fs, float fsz) {
    const unsigned* __restrict__ inb = dir ? &g_B[0][0] : &g_A[0][0];
    unsigned* __restrict__ outb = dir ? &g_A[0][0] : &g_B[0][0];
    int z0 = threadIdx.x * 2;
    int y = blockIdx.x * 4 + threadIdx.y;
    int x = blockIdx.y;
    int f = blockIdx.z;
    int idx = (x * NN + y) * NN + z0;
    const unsigned* vol = inb + (size_t)f * NVOX;

    uint2 cc = *reinterpret_cast<const uint2*>(vol + idx);
    float xm = __int_as_float(FMAGIC_I + x);
    float ym = __int_as_float(FMAGIC_I + y);
    int zmb = FMAGIC_I + z0;
    uint2 oo;

    #pragma unroll
    for (int h = 0; h < 2; h++) {
        unsigned u = h ? cc.y : cc.x;
        float vx = fmaf(dcx(u), inv,  co_x);
        float vy = fmaf(dcy(u), inv,  co_x);
        float vz = fmaf(dcz(u), inv2, co_z);

        int off; float fx, fy, fz;
        setup(vx, vy, vz, xm, ym, __int_as_float(zmb + h), &off, &fx, &fy, &fz);
        float3 w = fetchlerp(vol + off, fx, fy, fz);

        // t = v_new*fs_out + intbias/2; pack bias completes to stored format
        float tx = fmaf(w.x, 0.5f, fmaf(vx, fs,  -4194304.f));  // -2^22
        float ty = fmaf(w.y, 0.5f, fmaf(vy, fs,  -4194304.f));
        float tz = fmaf(w.z, 0.5f, fmaf(vz, fsz, -4194304.f));
        int px = cpack(tx, -512.f, 1535.f, 512);
        int py = cpack(ty, -512.f, 1535.f, 512);
        int pz = cpack(tz, -256.f, 767.f,  256);
        unsigned o = (unsigned)(px + (py << 11) + (pz << 22));
        if (h) oo.y = o; else oo.x = o;
    }
    *reinterpret_cast<uint2*>(outb + (size_t)f * NVOX + idx) = oo;
}

// Compose + residual norm, restructured by ref: blockIdx.z = r in {0,1,2} selects
// F_neg field 2r; pairs for ref r are (flo = j+1, j=r..2) with pair index pbase[r]+(j-r).
// Center decode + sample setup shared across the ref's pairs.
__constant__ int c_pbase[3] = {0, 3, 5};

__global__ void __launch_bounds__(192) k_final() {
    __shared__ double sred[6];
    const float inv  = 0.0078125f;      // 1/128
    const float inv2 = 0.015625f;       // 1/64
    const float co_x = -65544.f;        // -(2^23+1024)/128
    const float co_z = -131080.f;       // -(2^23+512)/64
    int z = threadIdx.x;
    int y = blockIdx.x * 2 + threadIdx.y;
    int x = blockIdx.y;
    int r = blockIdx.z;
    int idx = (x * NN + y) * NN + z;

    unsigned u = g_B[2 * r][idx];
    float vx = fmaf(dcx(u), inv,  co_x);
    float vy = fmaf(dcy(u), inv,  co_x);
    float vz = fmaf(dcz(u), inv2, co_z);

    int off; float fx, fy, fz;
    setup(vx, vy, vz,
          __int_as_float(FMAGIC_I + x), __int_as_float(FMAGIC_I + y),
          __int_as_float(FMAGIC_I + z), &off, &fx, &fy, &fz);

    float acc = 0.f;
    for (int j = r; j < 3; j++) {
        int p = c_pbase[r] + (j - r);
        const unsigned* vol = &g_B[2 * j + 1][0];
        float3 w = fetchlerp(vol + off, fx, fy, fz);
        float rx = fmaf(w.x, inv,  vx - g_Rt[0][p][idx]);
        float ry = fmaf(w.y, inv,  vy - g_Rt[1][p][idx]);
        float rz = fmaf(w.z, inv2, vz - g_Rt[2][p][idx]);
        acc += sqrtf(rx * rx + ry * ry + rz * rz);
    }

    #pragma unroll
    for (int o = 16; o; o >>= 1) acc += __shfl_down_sync(0xffffffffu, acc, o);

    int lin = threadIdx.y * NN + threadIdx.x;
    int lane = lin & 31, w = lin >> 5;
    if (lane == 0) sred[w] = (double)acc;
    __syncthreads();
    if (lin == 0) {
        double a = 0.0;
        #pragma unroll
        for (int i = 0; i < 6; i++) a += sred[i];
        g_part[r * BLK3 + blockIdx.x * NN + blockIdx.y] = a;
    }
}

// Deterministic final reduction
__global__ void __launch_bounds__(1024) k_reduce(float* __restrict__ out) {
    __shared__ double sred[32];
    double acc = 0.0;
    const int n = 3 * BLK3;
    for (int i = threadIdx.x; i < n; i += 1024) acc += g_part[i];
    #pragma unroll
    for (int o = 16; o; o >>= 1) acc += __shfl_down_sync(0xffffffffu, acc, o);
    int lane = threadIdx.x & 31, w = threadIdx.x >> 5;
    if (lane == 0) sred[w] = acc;
    __syncthreads();
    if (threadIdx.x == 0) {
        double tot = 0.0;
        #pragma unroll
        for (int i = 0; i < 32; i++) tot += sred[i];
        out[0] = (float)tot;
    }
}

extern "C" void kernel_launch(void* const* d_in, const int* in_sizes, int n_in,
                              void* d_out, int out_size) {
    const float* T = (const float*)d_in[0];
    const float* R = (const float*)d_in[1];
    if (n_in >= 2 && in_sizes[0] == 15925248) {   // robust to metadata ordering
        T = (const float*)d_in[1];
        R = (const float*)d_in[0];
    }
    float* out = (float*)d_out;

    dim3 bi(NN, 2);
    dim3 gi(48, NN, NFIELDS);
    k_init<<<gi, bi>>>(T);
    k_transpose<<<NBLKL, TPBL>>>(R);

    dim3 bs(48, 4);
    dim3 gs(24, NN, NFIELDS);
    for (int s = 0; s < VSTEPS; s++) {
        float inv  = ldexpf(1.f, s - 14);
        float inv2 = ldexpf(1.f, s - 13);
        float co_x = -(8388608.f + 1024.f) * inv;   // exact (2 mantissa bits)
        float co_z = -(8388608.f + 512.f)  * inv2;
        float fs   = ldexpf(1.f, 13 - s);
        float fsz  = ldexpf(1.f, 12 - s);
        k_step<<<gs, bs>>>(s & 1, inv, inv2, co_x, co_z, fs, fsz);  // ends in g_B
    }
    dim3 gf(48, NN, 3);
    k_final<<<gf, bi>>>();
    k_reduce<<<1, 1024>>>(out);
}

// round 11
// speedup vs baseline: 1.7493x; 1.0200x over previous
#include <cuda_runtime.h>

#define NN 96
#define NP 9216            // 96*96
#define NVOX 884736        // 96^3
#define NFIELDS 6          // fields the loss consumes: neg0,pos1,neg1,pos2,neg2,pos3
#define NFA 7              // +1 zero dummy field: OOB landing zone for weight-0 reads
#define NPAIRS 6
#define VSTEPS 7
#define TPBL 256
#define NBLKL (NVOX / TPBL)
#define BLK3 (48 * NN)     // k_final partial blocks per ref

// Field voxel = one uint32, Z-LOW biased layout:
//   bits[0:10)  pz = iz + 512, bits[10:21) px = ix + 1024, bits[21:32) py = iy + 1024
// Per-step range B_k = 2^k/16 (powers of two -> all scale folds exact).
__device__ __align__(16) unsigned g_A[NFA][NVOX];
__device__ __align__(16) unsigned g_B[NFA][NVOX];
__device__ float  g_Rt[3][NPAIRS][NVOX];   // transposed R + debias folds
__device__ double g_part[3 * BLK3];

#define MAGIC_I   0x4B000000u          // 2^23 float bits
#define FMAGIC    12582912.f           // 1.5 * 2^23
#define FMAGIC_I  0x4B400000

__device__ __forceinline__ float fadd_rm(float a, float b) {
    float r;
    asm("add.rm.f32 %0, %1, %2;" : "=f"(r) : "f"(a), "f"(b));
    return r;
}

// decodes (t = u >> 10)
__device__ __forceinline__ float dZ(unsigned u) { return __int_as_float((u & 0x3FFu) | MAGIC_I); }       // 2^23+pz
__device__ __forceinline__ float dX(unsigned t) { return __int_as_float((t & 0x7FFu) | MAGIC_I); }       // 2^23+px
__device__ __forceinline__ float dB(unsigned t) { return __int_as_float((t & 0x3FFFFFu) | MAGIC_I); }    // 2^23+px+2048py

// Sample setup: global floor via folded magic, fracs, reference clamp semantics:
// x0=clip(floor,0,95); HIGH side (floor>=95) kills frac (x1==x0 in reference);
// low side keeps unclamped frac (x0=0, x1=1). OOB corner reads get weight 0.
__device__ __forceinline__ void setup(float vx, float vy, float vz,
                                      float xm, float ym, float zm,
                                      int* off, float* fx, float* fy, float* fz) {
    float t;
    t = fadd_rm(vx, xm); int xi = __float_as_int(t) - FMAGIC_I; *fx = vx - (t - xm);
    t = fadd_rm(vy, ym); int yi = __float_as_int(t) - FMAGIC_I; *fy = vy - (t - ym);
    t = fadd_rm(vz, zm); int zi = __float_as_int(t) - FMAGIC_I; *fz = vz - (t - zm);
    if (xi >= NN - 1) *fx = 0.f;
    if (yi >= NN - 1) *fy = 0.f;
    if (zi >= NN - 1) *fz = 0.f;
    int x0 = min(max(xi, 0), NN - 1);
    int y0 = min(max(yi, 0), NN - 1);
    int z0 = min(max(zi, 0), NN - 1);
    *off = (x0 * NN + y0) * NN + z0;
}

// trilinear corner weights (order: A(x0y0z0) B(z1) C(y1) D(y1z1) E(x1) F G H)
__device__ __forceinline__ void mkweights(float fx, float fy, float fz, float* w) {
    float gx = 1.f - fx, gy = 1.f - fy, gz = 1.f - fz;
    float a00 = gy * gz, a01 = gy * fz, a10 = fy * gz, a11 = fy * fz;
    w[0] = gx * a00; w[1] = gx * a01; w[2] = gx * a10; w[3] = gx * a11;
    w[4] = fx * a00; w[5] = fx * a01; w[6] = fx * a10; w[7] = fx * a11;
}

// 8-corner gather + 3 weighted-dot chains. Returns (X̄b=2^23+X̄, 2048·Ȳ, Z̄b=2^23+Z̄).
__device__ __forceinline__ float3 fetchdot(const unsigned* __restrict__ p,
                                           const float* __restrict__ w) {
    unsigned u0 = __ldg(p),           u1 = __ldg(p + 1);
    unsigned u2 = __ldg(p + NN),      u3 = __ldg(p + NN + 1);
    unsigned u4 = __ldg(p + NP),      u5 = __ldg(p + NP + 1);
    unsigned u6 = __ldg(p + NP + NN), u7 = __ldg(p + NP + NN + 1);
    unsigned uu[8] = {u0, u1, u2, u3, u4, u5, u6, u7};
    float sX = 0.f, sB = 0.f, sZ = 0.f;
    #pragma unroll
    for (int i = 0; i < 8; i++) {
        unsigned t = uu[i] >> 10;
        sX = fmaf(w[i], dX(t), sX);
        sB = fmaf(w[i], dB(t), sB);
        sZ = fmaf(w[i], dZ(uu[i]), sZ);
    }
    return make_float3(sX, sB - sX, sZ);
}

// round-to-nearest pack with bias folded into the int subtract
__device__ __forceinline__ int cpack(float t, float lo, float hi, int bias) {
    float c = fminf(fmaxf(t, lo), hi) + FMAGIC;
    return __float_as_int(c) - (FMAGIC_I - bias);
}

// Field table: f -> transform index; sign = (f odd) ? + : -
__constant__ int c_ftp[NFIELDS] = {0, 1, 1, 2, 2, 3};

__global__ void __launch_bounds__(192) k_init(const float* __restrict__ T) {
    int z = threadIdx.x;
    int y = blockIdx.x * 2 + threadIdx.y;
    int x = blockIdx.y;
    int f = blockIdx.z;
    int idx = (x * NN + y) * NN + z;
    int tp = c_ftp[f];
    float s = (f & 1) ? 0.0078125f : -0.0078125f;
    const float* base = T + (size_t)tp * 3 * NVOX;
    int px = cpack(s * base[idx]            * 16384.f, -1023.f, 1023.f, 1024);
    int py = cpack(s * base[idx + NVOX]     * 16384.f, -1023.f, 1023.f, 1024);
    int pz = cpack(s * base[idx + 2 * NVOX] * 8192.f,  -511.f,  511.f,  512);
    g_A[f][idx] = (unsigned)(pz + (px << 10) + (py << 21));
}

// Transpose R (x,y,z,c,p) -> (c,p,voxel); fold debias consts (exact)
__global__ void __launch_bounds__(TPBL) k_transpose(const float* __restrict__ R) {
    __shared__ float s[TPBL * 18];
    int base = blockIdx.x * TPBL;
    for (int j = threadIdx.x; j < TPBL * 18; j += TPBL)
        s[j] = R[(size_t)base * 18 + j];
    __syncthreads();
    int idx = base + threadIdx.x;
    const float fold[3] = {65544.f, 8.f, 131080.f};  // (2^23+1024)/128, 1024/128, (2^23+512)/64
    #pragma unroll
    for (int c = 0; c < 3; c++)
        #pragma unroll
        for (int p = 0; p < NPAIRS; p++)
            g_Rt[c][p][idx] = s[threadIdx.x * 18 + c * 6 + p] + fold[c];
}

// One squaring step, 6 fields, FOUR z-voxels per thread.
// inv=2^(s-14), inv_y=2^(s-25), inv2=2^(s-13); co_* exact decode offsets;
// fs=2^(13-s), fsz=2^(12-s) with inv*fs = inv2*fsz = 0.5, inv_y*fs = 2^-12.
__global__ void __launch_bounds__(192) k_step(int dir, float inv, float inv_y, float inv2,
                                              float co_x, float co_y, float co_z,
                                              float fs, float fsz) {
    const unsigned* __restrict__ inb = dir ? &g_B[0][0] : &g_A[0][0];
    unsigned* __restrict__ outb = dir ? &g_A[0][0] : &g_B[0][0];
    int z0 = threadIdx.x * 4;
    int y = blockIdx.x * 8 + threadIdx.y;
    int x = blockIdx.y;
    int f = blockIdx.z;
    int idx = (x * NN + y) * NN + z0;
    const unsigned* vol = inb + (size_t)f * NVOX;

    uint4 cc = *reinterpret_cast<const uint4*>(vol + idx);
    unsigned cw[4] = {cc.x, cc.y, cc.z, cc.w};
    unsigned ow[4];
    float xm = __int_as_float(FMAGIC_I + x);
    float ym = __int_as_float(FMAGIC_I + y);
    int zmb = FMAGIC_I + z0;

    #pragma unroll
    for (int h = 0; h < 4; h++) {
        unsigned u = cw[h];
        unsigned t = u >> 10;
        float dx0 = dX(t);
        float vx = fmaf(dx0, inv, co_x);
        float vy = fmaf(dB(t) - dx0, inv_y, co_y);
        float vz = fmaf(dZ(u), inv2, co_z);

        int off; float fx, fy, fz;
        setup(vx, vy, vz, xm, ym, __int_as_float(zmb + h), &off, &fx, &fy, &fz);
        float w[8];
        mkweights(fx, fy, fz, w);
        float3 d = fetchdot(vol + off, w);

        // t* = v_new * fs_out directly (debias folded into exact constants)
        float tx = fmaf(d.x, 0.5f,             fmaf(vx, fs,  -4194816.f));  // -(2^23+1024)/2
        float ty = fmaf(d.y, 2.44140625e-4f,   fmaf(vy, fs,  -512.f));      // inv_y*fs = 2^-12
        float tz = fmaf(d.z, 0.5f,             fmaf(vz, fsz, -4194560.f));  // -(2^23+512)/2
        int px = cpack(tx, -1023.f, 1023.f, 1024);
        int py = cpack(ty, -1023.f, 1023.f, 1024);
        int pz = cpack(tz, -511.f,  511.f,  512);
        ow[h] = (unsigned)(pz + (px << 10) + (py << 21));
    }
    *reinterpret_cast<uint4*>(outb + (size_t)f * NVOX + idx) = make_uint4(ow[0], ow[1], ow[2], ow[3]);
}

// Compose + residual norm, by ref r in {0,1,2}: F_neg field = 2r; pairs share
// the center decode, sample setup AND trilinear weights; only gathers+dots per pair.
__constant__ int c_pbase[3] = {0, 3, 5};

__global__ void __launch_bounds__(192) k_final() {
    __shared__ double sred[6];
    const float inv  = 0.0078125f;      // 1/128
    const float invy = 3.814697265625e-6f;  // 2^-18
    const float inv2 = 0.015625f;       // 1/64
    const float co_x = -65544.f;        // -(2^23+1024)/128
    const float co_y = -8.f;            // -1024/128
    const float co_z = -131080.f;       // -(2^23+512)/64
    int z = threadIdx.x;
    int y = blockIdx.x * 2 + threadIdx.y;
    int x = blockIdx.y;
    int r = blockIdx.z;
    int idx = (x * NN + y) * NN + z;

    unsigned u = g_B[2 * r][idx];
    unsigned t = u >> 10;
    float dx0 = dX(t);
    float vx = fmaf(dx0, inv, co_x);
    float vy = fmaf(dB(t) - dx0, invy, co_y);
    float vz = fmaf(dZ(u), inv2, co_z);

    int off; float fx, fy, fz;
    setup(vx, vy, vz,
          __int_as_float(FMAGIC_I + x), __int_as_float(FMAGIC_I + y),
          __int_as_float(FMAGIC_I + z), &off, &fx, &fy, &fz);
    float w[8];
    mkweights(fx, fy, fz, w);

    float acc = 0.f;
    for (int j = r; j < 3; j++) {
        int p = c_pbase[r] + (j - r);
        float3 d = fetchdot(&g_B[2 * j + 1][0] + off, w);
        float rx = fmaf(d.x, inv,  vx - g_Rt[0][p][idx]);
        float ry = fmaf(d.y, invy, vy - g_Rt[1][p][idx]);
        float rz = fmaf(d.z, inv2, vz - g_Rt[2][p][idx]);
        acc += sqrtf(rx * rx + ry * ry + rz * rz);
    }

    #pragma unroll
    for (int o = 16; o; o >>= 1) acc += __shfl_down_sync(0xffffffffu, acc, o);

    int lin = threadIdx.y * NN + threadIdx.x;
    int lane = lin & 31, wi = lin >> 5;
    if (lane == 0) sred[wi] = (double)acc;
    __syncthreads();
    if (lin == 0) {
        double a = 0.0;
        #pragma unroll
        for (int i = 0; i < 6; i++) a += sred[i];
        g_part[r * BLK3 + blockIdx.x * NN + blockIdx.y] = a;
    }
}

// Deterministic final reduction
__global__ void __launch_bounds__(1024) k_reduce(float* __restrict__ out) {
    __shared__ double sred[32];
    double acc = 0.0;
    const int n = 3 * BLK3;
    for (int i = threadIdx.x; i < n; i += 1024) acc += g_part[i];
    #pragma unroll
    for (int o = 16; o; o >>= 1) acc += __shfl_down_sync(0xffffffffu, acc, o);
    int lane = threadIdx.x & 31, w = threadIdx.x >> 5;
    if (lane == 0) sred[w] = acc;
    __syncthreads();
    if (threadIdx.x == 0) {
        double tot = 0.0;
        #pragma unroll
        for (int i = 0; i < 32; i++) tot += sred[i];
        out[0] = (float)tot;
    }
}

extern "C" void kernel_launch(void* const* d_in, const int* in_sizes, int n_in,
                              void* d_out, int out_size) {
    const float* T = (const float*)d_in[0];
    const float* R = (const float*)d_in[1];
    if (n_in >= 2 && in_sizes[0] == 15925248) {   // robust to metadata ordering
        T = (const float*)d_in[1];
        R = (const float*)d_in[0];
    }
    float* out = (float*)d_out;

    dim3 bi(NN, 2);
    dim3 gi(48, NN, NFIELDS);
    k_init<<<gi, bi>>>(T);
    k_transpose<<<NBLKL, TPBL>>>(R);

    dim3 bs(24, 8);
    dim3 gs(12, NN, NFIELDS);
    for (int s = 0; s < VSTEPS; s++) {
        float inv   = ldexpf(1.f, s - 14);
        float inv_y = ldexpf(1.f, s - 25);
        float inv2  = ldexpf(1.f, s - 13);
        float co_x  = -(8388608.f + 1024.f) * inv;   // exact
        float co_y  = -ldexpf(1.f, s - 4);           // -1024*inv
        float co_z  = -(8388608.f + 512.f)  * inv2;
        float fs    = ldexpf(1.f, 13 - s);
        float fsz   = ldexpf(1.f, 12 - s);
        k_step<<<gs, bs>>>(s & 1, inv, inv_y, inv2, co_x, co_y, co_z, fs, fsz);  // ends in g_B
    }
    dim3 gf(48, NN, 3);
    k_final<<<gf, bi>>>();
    k_reduce<<<1, 1024>>>(out);
}